// round 17
// baseline (speedup 1.0000x reference)
#include <cuda_runtime.h>
#include <cuda_bf16.h>
#include <stdint.h>
#include <math.h>

#define VOCAB 32000
#define HID   512
#define EMB   256
#define NB    256
#define LEN   512

#define CL    8            // h-tile CTAs per n-tile (flag group size)
#define NTILE 16           // n rows per block
#define HTILE 64           // h cols per block
#define NT    16           // number of n-tiles
#define GRID  128
#define NTHR  512

typedef unsigned long long u64;

// Scratch (static device allocations are allowed; runtime allocs are not).
__device__ float g_P[VOCAB * HID];            // P = emb @ Wxh^T + b  (65.5 MB)
__device__ float g_h[2][NB * HID];            // ping-pong hidden state
__device__ unsigned g_flag[NT * CL * 64];     // per-producer flags, 256B apart
__device__ unsigned g_cnt[NT * 64];           // end-of-kernel cleanup counters

// Packed fp32x2 ops (B300 packed pipe; ptxas never emits these from C++).
__device__ __forceinline__ u64 ffma2(u64 a, u64 b, u64 c) {
    u64 d;
    asm("fma.rn.f32x2 %0, %1, %2, %3;" : "=l"(d) : "l"(a), "l"(b), "l"(c));
    return d;
}
__device__ __forceinline__ u64 fadd2(u64 a, u64 b) {
    u64 d;
    asm("add.rn.f32x2 %0, %1, %2;" : "=l"(d) : "l"(a), "l"(b));
    return d;
}

// ---------------------------------------------------------------------------
// proj_kernel v3 (unchanged from R16): weights in registers, emb via SMEM.
// ---------------------------------------------------------------------------
__global__ void __launch_bounds__(256, 2)
proj_kernel(const float* __restrict__ emb,
            const float* __restrict__ Wxh_w,
            const float* __restrict__ Wxh_b) {
    extern __shared__ float sm[];
    float*  As   = sm;                          // [64 v][256 k]  64 KB
    float2* red2 = (float2*)(sm + 64 * 256);    // 2 x [8 kg][8 v][32 l] 32 KB

    const int tid  = threadIdx.x;
    const int kg   = tid >> 5;
    const int lane = tid & 31;
    const int v0   = blockIdx.x * 64;
    const int h0   = blockIdx.y * 64;

    u64 wA[16], wB[16];
    {
        const u64* pa = (const u64*)&Wxh_w[(size_t)(h0 + 2 * lane) * EMB + kg * 32];
        const u64* pb = (const u64*)&Wxh_w[(size_t)(h0 + 2 * lane + 1) * EMB + kg * 32];
#pragma unroll
        for (int i = 0; i < 16; i++) { wA[i] = pa[i]; wB[i] = pb[i]; }
    }

    {
        const int r  = tid >> 2;
        const int cb = (tid & 3) * 64;
#pragma unroll
        for (int j = 0; j < 16; j++) {
            int c = cb + 4 * j;
            *(float4*)&As[r * 256 + c] =
                *(const float4*)&emb[(size_t)(v0 + r) * EMB + c];
        }
    }
    __syncthreads();

    const int    rv = tid >> 5;
    const int    rl = tid & 31;
    const float2 bv = *(const float2*)&Wxh_b[h0 + 2 * rl];

#pragma unroll 1
    for (int c = 0; c < 8; c++) {
        float2* buf = red2 + (c & 1) * 2048;

        u64 aA[8], aB[8];
#pragma unroll
        for (int n = 0; n < 8; n++) { aA[n] = 0ULL; aB[n] = 0ULL; }
        const float* hp = As + (c * 8) * 256 + kg * 32;
#pragma unroll
        for (int n = 0; n < 8; n++) {
            const float4* row = (const float4*)(hp + n * 256);
            u64 a0 = aA[n], a1 = aB[n];
#pragma unroll
            for (int j = 0; j < 8; j++) {
                float4 hv = row[j];
                u64 lo = ((const u64*)&hv)[0];
                u64 hi = ((const u64*)&hv)[1];
                a0 = ffma2(lo, wA[2 * j],     a0);
                a0 = ffma2(hi, wA[2 * j + 1], a0);
                a1 = ffma2(lo, wB[2 * j],     a1);
                a1 = ffma2(hi, wB[2 * j + 1], a1);
            }
            aA[n] = a0; aB[n] = a1;
        }
#pragma unroll
        for (int n = 0; n < 8; n++) {
            float2 fa = *(float2*)&aA[n];
            float2 fb = *(float2*)&aB[n];
            buf[kg * 256 + n * 32 + lane] =
                make_float2(fa.x + fa.y, fb.x + fb.y);
        }
        __syncthreads();

        u64 s = 0ULL;
#pragma unroll
        for (int g = 0; g < 8; g++) {
            u64 v = *(const u64*)&buf[g * 256 + rv * 32 + rl];
            s = fadd2(s, v);
        }
        float2 rr = *(float2*)&s;
        rr.x += bv.x; rr.y += bv.y;
        *(float2*)&g_P[(size_t)(v0 + c * 8 + rv) * HID + h0 + 2 * rl] = rr;
    }
}

// ---------------------------------------------------------------------------
// rnn_kernel: R11 structure + decoupled publish barrier + parity sm_red.
//   After the epilogue, 13 non-critical warps bar.arrive(1) and run ahead
//   into step t+1 (poll + cp.async + compute + STS into the OTHER sm_red
//   parity buffer), overlapping the publish/discovery latency. Warp 0
//   (publisher) and the 2 self-warps (whose next-step SMEM slice is written
//   by all threads' epilogue) bar.sync(1); tid0 then st.release's the flag.
//   Ordering: STG -> bar.arrive (membar.cta semantics) -> warp0 bar.sync ->
//   st.release.gpu -> consumer ld.acquire.gpu  (same chain as the proven
//   __syncthreads version). sm_red is double-buffered by step parity so
//   run-ahead STS can't race slow warps' reduce reads.
// ---------------------------------------------------------------------------
__global__ void __launch_bounds__(NTHR, 1)
rnn_kernel(const int*   __restrict__ X,
           const float* __restrict__ Whh_w,
           const float* __restrict__ Whh_b,
           float*       __restrict__ out)
{
    extern __shared__ float sm[];
    float*  sm_h    = sm;                        // [16 w][16 n][32 k]  32 KB
    float2* sm_red0 = (float2*)(sm + 16 * 512);  // parity 0: 64 KB
    float2* sm_red1 = sm_red0 + 8192;            // parity 1: 64 KB

    const int tid   = threadIdx.x;
    const int w     = tid >> 5;
    const int lane  = tid & 31;
    const int tile  = blockIdx.x >> 3;           // n-tile id (flag group)
    const int j_own = blockIdx.x & 7;            // own h-block id
    const int n0    = tile * NTILE;
    const int h0    = j_own * HTILE;
    const int hA    = h0 + 2 * lane;             // contiguous h pair
    const int hB    = hA + 1;

    const int  j_src     = w >> 1;               // producer this warp consumes
    const bool is_self   = (j_src == j_own);
    const bool sync_warp = (w == 0) || is_self;  // must wait at publish barrier

    // --- persistent weight registers: rows hA,hB, k in [32w, 32w+32) -------
    u64 wA[16], wB[16];
    {
        const u64* pa = (const u64*)&Whh_w[(size_t)hA * HID + w * 32];
        const u64* pb = (const u64*)&Whh_w[(size_t)hB * HID + w * 32];
#pragma unroll
        for (int i = 0; i < 16; i++) { wA[i] = pa[i]; wB[i] = pb[i]; }
    }

    unsigned int smem_w_base;
    {
        unsigned int a;
        asm("{ .reg .u64 t; cvta.to.shared.u64 t, %1; cvt.u32.u64 %0, t; }"
            : "=r"(a) : "l"(sm_h + w * 512));
        smem_w_base = a;
    }

    // epilogue ownership: thread (en, el) -> row n0+en, h-pair h0+2*el
    const int    en    = tid >> 5;
    const int    el    = tid & 31;
    const int    enab  = n0 + en;
    const float2 ebv   = *(const float2*)&Whh_b[h0 + 2 * el];
    // SMEM destination for own slice: warp 2*j_own + (el>=16), [n=en][kk=2el&31]
    float* sm_self = &sm_h[(2 * j_own + (el >> 4)) * 512 + en * 32 + ((2 * el) & 31)];

    unsigned* my_flag  = &g_flag[(tile * CL + j_own) * 64];
    unsigned* src_flag = &g_flag[(tile * CL + j_src) * 64];

    // preload step-0 gather
    float2 pv;
    {
        int xid = __ldg(&X[enab * LEN]);
        pv = __ldg((const float2*)&g_P[(size_t)xid * HID + h0 + 2 * el]);
    }

    for (int t = 0; t < LEN; t++) {
        float* dst = (t == LEN - 1) ? out : ((t & 1) ? g_h[1] : g_h[0]);
        const float* hin = (t & 1) ? g_h[0] : g_h[1];
        float2* sm_red = (t & 1) ? sm_red1 : sm_red0;

        float sA = 0.f, sB = 0.f;

        if (t > 0) {
            if (!is_self) {
                // --- wait for our single producer -----------------------------
                if (lane == 0) {
                    unsigned g;
                    do {
                        asm volatile("ld.acquire.gpu.u32 %0, [%1];"
                                     : "=r"(g) : "l"(src_flag) : "memory");
                    } while (g < (unsigned)t);
                }
                __syncwarp();
                // --- pull its slice in TWO commit groups (rows 0-7, 8-15) ----
#pragma unroll
                for (int half = 0; half < 2; half++) {
#pragma unroll
                    for (int i = 0; i < 2; i++) {
                        int c  = half * 64 + i * 32 + lane;  // 16B chunk (0..127)
                        int n  = c >> 3;
                        int kq = c & 7;
                        const float* src =
                            &hin[(size_t)(n0 + n) * HID + w * 32 + kq * 4];
                        asm volatile("cp.async.cg.shared.global [%0], [%1], 16;"
                                     :: "r"(smem_w_base + c * 16), "l"(src)
                                     : "memory");
                    }
                    asm volatile("cp.async.commit_group;" ::: "memory");
                }
            }
            // (self warps: slice already in SMEM from last step's epilogue)

            // --- compute in two n-halves of 8; half 0 under half 1's arrival
#pragma unroll
            for (int half = 0; half < 2; half++) {
                if (!is_self) {
                    if (half == 0)
                        asm volatile("cp.async.wait_group 1;" ::: "memory");
                    else
                        asm volatile("cp.async.wait_group 0;" ::: "memory");
                }
                u64 aA[8], aB[8];
#pragma unroll
                for (int n = 0; n < 8; n++) { aA[n] = 0ULL; aB[n] = 0ULL; }
                const float* hp = sm_h + w * 512 + half * 8 * 32;
#pragma unroll
                for (int n = 0; n < 8; n++) {
                    const float4* row = (const float4*)(hp + n * 32);
                    u64 a0 = aA[n], a1 = aB[n];
#pragma unroll
                    for (int j = 0; j < 8; j++) {
                        float4 hv = row[j];
                        u64 lo = ((const u64*)&hv)[0];
                        u64 hi = ((const u64*)&hv)[1];
                        a0 = ffma2(lo, wA[2 * j],     a0);
                        a0 = ffma2(hi, wA[2 * j + 1], a0);
                        a1 = ffma2(lo, wB[2 * j],     a1);
                        a1 = ffma2(hi, wB[2 * j + 1], a1);
                    }
                    aA[n] = a0; aB[n] = a1;
                }
#pragma unroll
                for (int n = 0; n < 8; n++) {
                    float2 fa = *(float2*)&aA[n];
                    float2 fb = *(float2*)&aB[n];
                    sm_red[w * 512 + (half * 8 + n) * 32 + lane] =
                        make_float2(fa.x + fa.y, fb.x + fb.y);
                }
            }
            __syncthreads();                     // all partials of step t in buf

            // --- k-group reduction, packed f32x2 ------------------------------
            u64 r1 = 0ULL, r2 = 0ULL;
#pragma unroll
            for (int g = 0; g < 16; g += 2) {
                u64 v0 = *(const u64*)&sm_red[g * 512 + tid];
                u64 v1 = *(const u64*)&sm_red[(g + 1) * 512 + tid];
                r1 = fadd2(r1, v0);
                r2 = fadd2(r2, v1);
            }
            u64 rt = fadd2(r1, r2);
            float2 rr = *(float2*)&rt;
            sA = rr.x; sB = rr.y;
        }

        // --- fused epilogue: bias + P + tanh; publish to GMEM + own SMEM -----
        float2 o;
        o.x = tanhf(sA + ebv.x + pv.x);
        o.y = tanhf(sB + ebv.y + pv.y);
        *(float2*)&dst[(size_t)enab * HID + h0 + 2 * el] = o;
        *(float2*)sm_self = o;                 // self-warps read this next step

        if (t < LEN - 1) {
            // prefetch next step's gather (g_P immutable; hides across steps)
            int xid2 = __ldg(&X[enab * LEN + t + 1]);
            pv = __ldg((const float2*)&g_P[(size_t)xid2 * HID + h0 + 2 * el]);

            if (t == 0) {
                // step 0 keeps the simple full-barrier publish
                __syncthreads();
                if (tid == 0)
                    asm volatile("st.release.gpu.u32 [%0], %1;"
                                 :: "l"(my_flag), "r"(1u) : "memory");
            } else if (sync_warp) {
                // publisher + self-warps wait for ALL epilogue stores
                asm volatile("bar.sync 1, %0;" :: "r"(NTHR) : "memory");
                if (tid == 0)
                    asm volatile("st.release.gpu.u32 [%0], %1;"
                                 :: "l"(my_flag), "r"((unsigned)(t + 1)) : "memory");
            } else {
                // fast warps: signal and run ahead into step t+1
                asm volatile("bar.arrive 1, %0;" :: "r"(NTHR) : "memory");
            }
        }
    }

    // --- end-of-kernel cleanup: last CTA of the group resets flags/counter --
    __syncthreads();
    if (tid == 0) {
        unsigned old;
        asm volatile("atom.acq_rel.gpu.global.add.u32 %0, [%1], %2;"
                     : "=r"(old) : "l"(&g_cnt[tile * 64]), "r"(1u) : "memory");
        if (old == CL - 1) {
#pragma unroll
            for (int j = 0; j < CL; j++)
                asm volatile("st.relaxed.gpu.u32 [%0], %1;"
                             :: "l"(&g_flag[(tile * CL + j) * 64]), "r"(0u)
                             : "memory");
            asm volatile("st.relaxed.gpu.u32 [%0], %1;"
                         :: "l"(&g_cnt[tile * 64]), "r"(0u) : "memory");
        }
    }
}

// ---------------------------------------------------------------------------
extern "C" void kernel_launch(void* const* d_in, const int* in_sizes, int n_in,
                              void* d_out, int out_size) {
    const int*   X     = (const int*)d_in[0];
    const float* emb   = (const float*)d_in[1];
    const float* Whh_w = (const float*)d_in[2];
    const float* Whh_b = (const float*)d_in[3];
    const float* Wxh_w = (const float*)d_in[4];
    const float* Wxh_b = (const float*)d_in[5];
    float* out = (float*)d_out;

    const size_t sm_proj = (size_t)(64 * 256 + 2 * 2048 * 2) * sizeof(float);  // 96 KB
    const size_t sm_rnn  = (size_t)(16 * 512) * sizeof(float)                  // 32 KB h
                         + (size_t)(2 * 8192) * sizeof(float2);                // 128 KB red x2
    cudaFuncSetAttribute(proj_kernel, cudaFuncAttributeMaxDynamicSharedMemorySize, (int)sm_proj);
    cudaFuncSetAttribute(rnn_kernel,  cudaFuncAttributeMaxDynamicSharedMemorySize, (int)sm_rnn);

    // 1) P = emb @ Wxh^T + Wxh_b   (64v x 64h tiles, weights in registers)
    proj_kernel<<<dim3(VOCAB / 64, HID / 64), 256, sm_proj>>>(emb, Wxh_w, Wxh_b);

    // 2) all 512 timesteps in one persistent launch
    rnn_kernel<<<GRID, NTHR, sm_rnn>>>(X, Whh_w, Whh_b, out);
}